// round 10
// baseline (speedup 1.0000x reference)
#include <cuda_runtime.h>

// SPNBP compute_quant_to_alphabet — 4-lanes-per-k active-edge scatter + markers.
//
// out[n,b] = T[b+1] - T[b],  T[j] = sum_k w_k * e_j^k,
//   e_0 = 0, e_256 = 1, e_j = Phi(basec_k + (j-128)*inv_k)  (increasing in j).
//
// Phi (A&S 26.2.17, pdf constant folded into the poly) saturates EXACTLY in
// fp32 at |x| >= 5.5 (e*p < 2^-25 there). Split T = A + prefix(m):
//   A[j]    += w_k * Phi(cc_j)   only for active edges j in [jlo_k, jsat_k)
//   m[jsat] += w_k               (step part: Phi == 1 for all j >= jsat)
// The prefix cancels in the difference:  out[b] = A[b+1] - A[b] + m[b+1].
// No shuffles, no neighbor coupling -> any lane<->edge mapping works.
//
// One block per n, 256 threads. k = tid>>2 (8 k's per warp, all warps busy),
// each k's window walked by its 4 lanes stride-4 (~3 iters avg). Scatter via
// smem atomicAdd into 4 accumulators (one per warp pair). Two barriers total,
// no serial phases.

#define NBINS 256
#define KMAX  64
#define NACC  4

__device__ __forceinline__ float phi_fast(float x)
{
    const float ax = fabsf(x);
    const float t  = __frcp_rn(fmaf(0.2316419f, ax, 1.0f));
    // poly coefficients pre-scaled by 1/sqrt(2*pi) = 0.3989422804
    float p = fmaf(0.53070271f, t, -0.72657598f);
    p = fmaf(p, t,  0.71070688f);
    p = fmaf(p, t, -0.14224835f);
    p = fmaf(p, t,  0.12741479f);
    p = p * t;
    const float e = exp2f(-0.72134752f * ax * ax);   // log2(e)/2 folded
    const float y = fmaf(-e, p, 1.0f);               // Phi(|x|), ==1 for ax>=5.45
    return (x >= 0.0f) ? y : (1.0f - y);
}

__global__ __launch_bounds__(NBINS)
void spnbp_kernel(const float* __restrict__ Q,
                  const float* __restrict__ Q0,
                  const float* __restrict__ base_mean,
                  const float* __restrict__ base_var,
                  const float* __restrict__ mix_p,
                  float* __restrict__ out,
                  int N, int K)
{
    const int n   = blockIdx.x;
    const int tid = threadIdx.x;

    __shared__ alignas(16) float  s_A[NACC][258];  // edge accumulators (+pad)
    __shared__ alignas(16) float  s_m[258];        // saturation markers
    __shared__ float4             s_kc[KMAX];      // (basec, inv, w, pack(jlo,nE))

    // ---- phase 0: zero accumulators + per-k window computation ----
    {
        float4* z = (float4*)&s_A[0][0];           // NACC*258 = 1032 floats
        z[tid] = make_float4(0.f, 0.f, 0.f, 0.f);  // 1024
        if (tid < 2) z[256 + tid] = make_float4(0.f, 0.f, 0.f, 0.f);
        s_m[tid] = 0.0f;
        if (tid == 0) { s_m[256] = 0.0f; s_m[257] = 0.0f; }
    }
    if (tid < KMAX) {
        float basec = 0.0f, inv = 1.0f, w = 0.0f;
        int   jlo = 1, nE = 0;
        if (tid < K) {
            const float qd  = Q[(size_t)n * N + n];     // diag(Q)[n]
            const float q0  = Q0[n];
            const float bm  = base_mean[tid * N + n];
            const float bv  = base_var [tid * N + n];
            w   = mix_p[tid * N + n];
            inv = rsqrtf(qd * qd * bv);
            basec = (-qd * bm - q0) * inv;
            const float rinv = __frcp_rn(inv);
            // cc crosses -5.5 at tlo, +5.5 at thi (cc increasing in j)
            const float tlo = fmaf(-5.5f - basec, rinv, 128.0f);
            const float thi = fmaf( 5.5f - basec, rinv, 128.0f);
            // j < jlo  -> cc < -5.5 -> Phi exact 0   (and forced e_0 = 0)
            // j >= jsat-> cc >= 5.5 -> Phi exact 1   (and forced e_256 = 1)
            jlo = __float2int_rd(fminf(fmaxf(tlo, 1.0f), 256.0f));
            int jsat = __float2int_ru(fminf(fmaxf(thi, 0.0f), 256.0f));
            if (jsat < jlo) jsat = jlo;
            nE = jsat - jlo;                            // <= ~23 here
        }
        s_kc[tid] = make_float4(basec, inv, w, __int_as_float(jlo | (nE << 16)));
    }
    __syncthreads();

    // ---- phase 1: scatter (all 256 threads; 4 lanes per k) ----
    {
        const int    k   = tid >> 2;
        const int    sub = tid & 3;
        const float4 c   = s_kc[k];                 // broadcast per 4 lanes
        const int    pk  = __float_as_int(c.w);
        const int    jlo = pk & 0xffff;
        const int    nE  = pk >> 16;
        float* __restrict__ acc = s_A[tid >> 6];    // one buffer per warp pair

        if (sub == 0)                               // step mass at jsat = jlo+nE
            atomicAdd(&s_m[jlo + nE], c.z);

        float cc = fmaf((float)(jlo + sub - 128), c.y, c.x);
        const float inv4 = 4.0f * c.y;
        for (int i = sub; i < nE; i += 4) {
            atomicAdd(&acc[jlo + i], c.z * phi_fast(cc));
            cc += inv4;
        }
    }
    __syncthreads();

    // ---- phase 2: reduce + diff + coalesced store ----
    float d = s_m[tid + 1];
    #pragma unroll
    for (int a = 0; a < NACC; ++a)
        d += s_A[a][tid + 1] - s_A[a][tid];         // A[0]=A[256]=0 by constr.
    out[(size_t)n * NBINS + tid] = d;
}

extern "C" void kernel_launch(void* const* d_in, const int* in_sizes, int n_in,
                              void* d_out, int out_size)
{
    const float* Q     = (const float*)d_in[0];   // [N, N]
    const float* Q0    = (const float*)d_in[1];   // [N, 1]
    const float* bmean = (const float*)d_in[2];   // [K, N]
    const float* bvar  = (const float*)d_in[3];   // [K, N]
    const float* mp    = (const float*)d_in[4];   // [K, N, 1]
    float* out = (float*)d_out;                   // [N, 256]

    const int N = in_sizes[1];                    // 1024
    const int K = in_sizes[2] / N;                // 64

    spnbp_kernel<<<N, NBINS>>>(Q, Q0, bmean, bvar, mp, out, N, K);
}

// round 11
// speedup vs baseline: 1.0201x; 1.0201x over previous
#include <cuda_runtime.h>

// SPNBP compute_quant_to_alphabet — warp-per-k scatter + saturation markers.
//
// out[n,b] = T[b+1] - T[b],  T[j] = sum_k w_k * e_j^k,
//   e_0 = 0, e_256 = 1, e_j = Phi(basec_k + (j-128)*inv_k) (increasing in j).
//
// Phi (A&S 26.2.17, pdf constant folded into the poly) saturates EXACTLY in
// fp32 at |x| >= 5.5. Decompose T = A + prefix(m):
//   A[j]    += w_k * Phi(cc_j)  for active edges j in [jlo_k, jsat_k)  (<= ~22)
//   m[jsat] += w_k              (Phi == 1 for all j >= jsat)
// prefix cancels in the diff:  out[b] = A[b+1] - A[b] + m[b+1].
// Corner cases (all mass left/right of range) degenerate to nE = 0 + marker.
//
// One block per n, 512 threads / 16 warps. Warp w owns k = w, w+16, w+32,
// w+48: 4 fully-unrolled passes, lanes <-> edges of ONE k per pass ->
// conflict-free plain smem RMW into a per-warp private accumulator (no
// atomics, no shuffles, no divergence-max penalty). All window math +
// marker adds live in the 64-thread prologue. Two barriers total.

#define NBINS 256
#define KMAX  64
#define NW    16
#define TPB   (NW * 32)

__device__ __forceinline__ float phi_fast(float x)
{
    const float ax = fabsf(x);
    const float t  = __frcp_rn(fmaf(0.2316419f, ax, 1.0f));
    // A&S 26.2.17 coefficients pre-scaled by 1/sqrt(2*pi)
    float p = fmaf(0.53070271f, t, -0.72657598f);
    p = fmaf(p, t,  0.71070688f);
    p = fmaf(p, t, -0.14224835f);
    p = fmaf(p, t,  0.12741479f);
    p = p * t;
    const float e = exp2f(-0.72134752f * ax * ax);   // log2(e)/2 folded
    const float y = fmaf(-e, p, 1.0f);               // Phi(|x|); ==1 for ax>=5.5
    return (x >= 0.0f) ? y : (1.0f - y);
}

__global__ __launch_bounds__(TPB)
void spnbp_kernel(const float* __restrict__ Q,
                  const float* __restrict__ Q0,
                  const float* __restrict__ base_mean,
                  const float* __restrict__ base_var,
                  const float* __restrict__ mix_p,
                  float* __restrict__ out,
                  int N, int K)
{
    const int n    = blockIdx.x;
    const int tid  = threadIdx.x;
    const int warp = tid >> 5;
    const int lane = tid & 31;

    __shared__ float4 s_kc[KMAX];             // (basec, inv, w, pack(jlo,nE))
    __shared__ float  s_A[NW][NBINS + 2];     // per-warp private accumulators
    __shared__ float  s_m[NBINS + 2];         // saturation markers

    // ---- phase 0: zero + per-k window computation ----
    {
        float* z = &s_A[0][0];                // NW*(NBINS+2) = 4128 floats
        #pragma unroll
        for (int i = tid; i < NW * (NBINS + 2); i += TPB) z[i] = 0.0f;
        if (tid < NBINS + 2) s_m[tid] = 0.0f;
    }
    if (tid < KMAX) {
        float basec = 0.0f, inv = 1.0f, w = 0.0f;
        int   jlo = 1, jsat = 1;
        if (tid < K) {
            const float qd  = Q[(size_t)n * N + n];     // diag(Q)[n]
            const float q0  = Q0[n];
            const float bm  = base_mean[tid * N + n];
            const float bv  = base_var [tid * N + n];
            w   = mix_p[tid * N + n];
            inv = rsqrtf(qd * qd * bv);
            basec = (-qd * bm - q0) * inv;
            const float rinv = __frcp_rn(inv);
            // cc crosses -5.5 at tlo, +5.5 at thi (cc increasing in j)
            const float tlo = fmaf(-5.5f - basec, rinv, 128.0f);
            const float thi = fmaf( 5.5f - basec, rinv, 128.0f);
            // j < jlo: Phi exact 0 (incl. forced e_0); j >= jsat: Phi exact 1
            // (incl. forced e_256)
            jlo  = __float2int_rd(fminf(fmaxf(tlo, 1.0f), 256.0f));
            jsat = __float2int_ru(fminf(fmaxf(thi, 0.0f), 256.0f));
            if (jsat < jlo) jsat = jlo;
        }
        s_kc[tid] = make_float4(basec, inv, w,
                                __int_as_float(jlo | ((jsat - jlo) << 16)));
        atomicAdd(&s_m[jsat], w);             // step mass (Phi==1 for j>=jsat)
    }
    __syncthreads();

    // ---- phase 1: scatter — 4 fully-unrolled warp-per-k passes ----
    {
        float* __restrict__ acc = s_A[warp];
        #pragma unroll
        for (int p = 0; p < KMAX / NW; ++p) {
            const float4 c   = s_kc[warp + p * NW];     // LDS.128 broadcast
            const int    pk  = __float_as_int(c.w);
            const int    jlo = pk & 0xffff;
            const int    nE  = pk >> 16;                // <= ~22 here
            if (lane < nE) {
                const float cc = fmaf((float)(jlo + lane - 128), c.y, c.x);
                acc[jlo + lane] += c.z * phi_fast(cc);  // conflict-free RMW
            }
            if (nE > 32) {                              // cold, never taken here
                for (int i = 32 + lane; i < nE; i += 32) {
                    const float cc = fmaf((float)(jlo + i - 128), c.y, c.x);
                    acc[jlo + i] += c.z * phi_fast(cc);
                }
            }
        }
    }
    __syncthreads();

    // ---- phase 2: reduce + diff + coalesced store ----
    if (tid < NBINS) {
        float d = s_m[tid + 1];
        #pragma unroll
        for (int i = 0; i < NW; ++i)
            d += s_A[i][tid + 1] - s_A[i][tid];   // A[0] = A[256] = 0 by constr.
        out[(size_t)n * NBINS + tid] = d;
    }
}

extern "C" void kernel_launch(void* const* d_in, const int* in_sizes, int n_in,
                              void* d_out, int out_size)
{
    const float* Q     = (const float*)d_in[0];   // [N, N]
    const float* Q0    = (const float*)d_in[1];   // [N, 1]
    const float* bmean = (const float*)d_in[2];   // [K, N]
    const float* bvar  = (const float*)d_in[3];   // [K, N]
    const float* mp    = (const float*)d_in[4];   // [K, N, 1]
    float* out = (float*)d_out;                   // [N, 256]

    const int N = in_sizes[1];                    // 1024
    const int K = in_sizes[2] / N;                // 64

    spnbp_kernel<<<N, TPB>>>(Q, Q0, bmean, bvar, mp, out, N, K);
}

// round 12
// speedup vs baseline: 1.2149x; 1.1910x over previous
#include <cuda_runtime.h>

// SPNBP compute_quant_to_alphabet — warp-per-k scatter + saturation markers,
// 256-thread blocks (single-wave residency: 1024 blocks <= 8/SM x 148 SMs).
//
// out[n,b] = T[b+1] - T[b],  T[j] = sum_k w_k * e_j^k,
//   e_0 = 0, e_256 = 1, e_j = Phi(basec_k + (j-128)*inv_k) (increasing in j).
//
// Phi (A&S 26.2.17, pdf constant folded into the poly) saturates EXACTLY in
// fp32 at |x| >= 5.5. Decompose T = A + prefix(m):
//   A[j]    += w_k * Phi(cc_j)  for active edges j in [jlo_k, jsat_k)  (<= ~22)
//   m[jsat] += w_k              (Phi == 1 for all j >= jsat)
// prefix cancels in the diff:  out[b] = A[b+1] - A[b] + m[b+1].
// Corner cases (all mass left/right of range) degenerate to nE = 0 + marker.
//
// One block per n, 8 warps. Warp w owns k = w, w+8, ..., w+56: 8 fully
// unrolled passes, lanes <-> edges of ONE k per pass -> conflict-free plain
// smem RMW into a per-warp private accumulator (no atomics, no shuffles).
// All window math + marker adds live in the 64-thread prologue. Two barriers.

#define NBINS 256
#define KMAX  64
#define NW    8
#define TPB   (NW * 32)

__device__ __forceinline__ float phi_fast(float x)
{
    const float ax = fabsf(x);
    const float t  = __frcp_rn(fmaf(0.2316419f, ax, 1.0f));
    // A&S 26.2.17 coefficients pre-scaled by 1/sqrt(2*pi)
    float p = fmaf(0.53070271f, t, -0.72657598f);
    p = fmaf(p, t,  0.71070688f);
    p = fmaf(p, t, -0.14224835f);
    p = fmaf(p, t,  0.12741479f);
    p = p * t;
    const float e = exp2f(-0.72134752f * ax * ax);   // log2(e)/2 folded
    const float y = fmaf(-e, p, 1.0f);               // Phi(|x|); ==1 for ax>=5.5
    return (x >= 0.0f) ? y : (1.0f - y);
}

__global__ __launch_bounds__(TPB)
void spnbp_kernel(const float* __restrict__ Q,
                  const float* __restrict__ Q0,
                  const float* __restrict__ base_mean,
                  const float* __restrict__ base_var,
                  const float* __restrict__ mix_p,
                  float* __restrict__ out,
                  int N, int K)
{
    const int n    = blockIdx.x;
    const int tid  = threadIdx.x;
    const int warp = tid >> 5;
    const int lane = tid & 31;

    __shared__ float4 s_kc[KMAX];                      // (basec, inv, w, pack)
    __shared__ alignas(16) float s_A[NW][NBINS + 4];   // per-warp accumulators
    __shared__ alignas(16) float s_m[NBINS + 4];       // saturation markers

    // ---- phase 0: zero accumulators/markers + per-k window computation ----
    {
        float4* z = (float4*)&s_A[0][0];               // NW*(NBINS+4)/4 = 520
        #pragma unroll
        for (int i = tid; i < NW * (NBINS + 4) / 4; i += TPB)
            z[i] = make_float4(0.f, 0.f, 0.f, 0.f);
        ((float4*)s_m)[tid & 63] = make_float4(0.f, 0.f, 0.f, 0.f); // 65 f4s:
        if (tid == 64) ((float4*)s_m)[64] = make_float4(0.f, 0.f, 0.f, 0.f);
    }
    if (tid < KMAX) {
        float basec = 0.0f, inv = 1.0f, w = 0.0f;
        int   jlo = 1, jsat = 1;
        if (tid < K) {
            const float qd  = Q[(size_t)n * N + n];    // diag(Q)[n]
            const float q0  = Q0[n];
            const float bm  = base_mean[tid * N + n];
            const float bv  = base_var [tid * N + n];
            w   = mix_p[tid * N + n];
            inv = rsqrtf(qd * qd * bv);
            basec = (-qd * bm - q0) * inv;
            const float rinv = __frcp_rn(inv);
            // cc crosses -5.5 at tlo, +5.5 at thi (cc increasing in j)
            const float tlo = fmaf(-5.5f - basec, rinv, 128.0f);
            const float thi = fmaf( 5.5f - basec, rinv, 128.0f);
            // j < jlo: Phi exact 0 (incl. forced e_0); j >= jsat: Phi exact 1
            // (incl. forced e_256)
            jlo  = __float2int_rd(fminf(fmaxf(tlo, 1.0f), 256.0f));
            jsat = __float2int_ru(fminf(fmaxf(thi, 0.0f), 256.0f));
            if (jsat < jlo) jsat = jlo;
        }
        s_kc[tid] = make_float4(basec, inv, w,
                                __int_as_float(jlo | ((jsat - jlo) << 16)));
        atomicAdd(&s_m[jsat], w);              // step mass (Phi==1 for j>=jsat)
    }
    __syncthreads();

    // ---- phase 1: scatter — 8 fully-unrolled warp-per-k passes ----
    {
        float* __restrict__ acc = s_A[warp];
        #pragma unroll
        for (int p = 0; p < KMAX / NW; ++p) {
            const float4 c   = s_kc[warp + p * NW];     // LDS.128 broadcast
            const int    pk  = __float_as_int(c.w);
            const int    jlo = pk & 0xffff;
            const int    nE  = pk >> 16;                // <= ~22 here
            if (lane < nE) {
                const float cc = fmaf((float)(jlo + lane - 128), c.y, c.x);
                acc[jlo + lane] += c.z * phi_fast(cc);  // conflict-free RMW
            }
            if (nE > 32) {                              // cold, never taken here
                for (int i = 32 + lane; i < nE; i += 32) {
                    const float cc = fmaf((float)(jlo + i - 128), c.y, c.x);
                    acc[jlo + i] += c.z * phi_fast(cc);
                }
            }
        }
    }
    __syncthreads();

    // ---- phase 2: reduce + diff + coalesced store ----
    {
        float d = s_m[tid + 1];
        #pragma unroll
        for (int i = 0; i < NW; ++i)
            d += s_A[i][tid + 1] - s_A[i][tid];   // A[0] = A[256] = 0 by constr.
        out[(size_t)n * NBINS + tid] = d;
    }
}

extern "C" void kernel_launch(void* const* d_in, const int* in_sizes, int n_in,
                              void* d_out, int out_size)
{
    const float* Q     = (const float*)d_in[0];   // [N, N]
    const float* Q0    = (const float*)d_in[1];   // [N, 1]
    const float* bmean = (const float*)d_in[2];   // [K, N]
    const float* bvar  = (const float*)d_in[3];   // [K, N]
    const float* mp    = (const float*)d_in[4];   // [K, N, 1]
    float* out = (float*)d_out;                   // [N, 256]

    const int N = in_sizes[1];                    // 1024
    const int K = in_sizes[2] / N;                // 64

    spnbp_kernel<<<N, TPB>>>(Q, Q0, bmean, bvar, mp, out, N, K);
}

// round 14
// speedup vs baseline: 1.2446x; 1.0245x over previous
#include <cuda_runtime.h>

// SPNBP compute_quant_to_alphabet — fully warp-decoupled scatter + markers.
//
// out[n,b] = T[b+1] - T[b],  T[j] = sum_k w_k * e_j^k,
//   e_0 = 0, e_256 = 1, e_j = Phi(basec_k + (j-128)*inv_k) (increasing in j).
//
// Phi (A&S 26.2.17, pdf constant folded) saturates EXACTLY in fp32 at
// |x| >= 5.5. Decompose T = A + prefix(m):
//   A[j]    += w_k * Phi(cc_j)  for active edges j in [jlo_k, jsat_k) (<= ~22)
//   m[jsat] += w_k              (Phi == 1 for all j >= jsat)
// prefix cancels in the diff: out[b] = A[b+1] - A[b] + m[b+1].
//
// One block per n (grid 1024 = single wave at 256 thr), 8 warps. Each warp is
// SELF-CONTAINED: zeroes its own accumulator/marker arrays, lanes 0-7 load +
// compute the constants for its 8 k's (k = w + 8l), __syncwarp, then 8
// unrolled scatter passes into its private arrays (plain conflict-free RMW).
// No cross-warp coupling -> exactly ONE __syncthreads (before the reduce);
// each warp starts computing as soon as ITS prologue loads land.

#define NBINS 256
#define KMAX  64
#define NW    8
#define TPB   (NW * 32)
#define ASZ   260                  // per-array stride (256+pad, 4-bank skew)

__device__ __forceinline__ float phi_fast(float x)
{
    const float ax = fabsf(x);
    const float t  = __frcp_rn(fmaf(0.2316419f, ax, 1.0f));
    // A&S 26.2.17 coefficients pre-scaled by 1/sqrt(2*pi)
    float p = fmaf(0.53070271f, t, -0.72657598f);
    p = fmaf(p, t,  0.71070688f);
    p = fmaf(p, t, -0.14224835f);
    p = fmaf(p, t,  0.12741479f);
    p = p * t;
    const float e = exp2f(-0.72134752f * ax * ax);   // log2(e)/2 folded
    const float y = fmaf(-e, p, 1.0f);               // Phi(|x|); ==1 for ax>=5.5
    return (x >= 0.0f) ? y : (1.0f - y);
}

__global__ __launch_bounds__(TPB)
void spnbp_kernel(const float* __restrict__ Q,
                  const float* __restrict__ Q0,
                  const float* __restrict__ base_mean,
                  const float* __restrict__ base_var,
                  const float* __restrict__ mix_p,
                  float* __restrict__ out,
                  int N, int K)
{
    const int n    = blockIdx.x;
    const int tid  = threadIdx.x;
    const int warp = tid >> 5;
    const int lane = tid & 31;

    // per-warp: [0] = A (edge sums), [1] = M (saturation markers)
    __shared__ alignas(16) float  s_AM[NW][2][ASZ];
    __shared__ alignas(16) float4 s_kc[NW][NW];      // staged per-k constants

    // ---- per-warp zeroing of own arrays (no cross-warp ordering) ----
    {
        float4* z = (float4*)&s_AM[warp][0][0];      // 2*ASZ/4 = 130 float4
        #pragma unroll
        for (int i = lane; i < 2 * ASZ / 4; i += 32)
            z[i] = make_float4(0.f, 0.f, 0.f, 0.f);
    }

    // ---- lanes 0-7: constants for this warp's 8 k's (k = warp + 8*lane) ----
    if (lane < NW) {
        const int k = warp + (lane << 3);
        float basec = 0.0f, inv = 1.0f, w = 0.0f;
        int   jlo = 1, jsat = 1;
        if (k < K) {
            const float qd  = Q[(size_t)n * N + n];    // diag(Q)[n]
            const float q0  = Q0[n];
            const float bm  = base_mean[k * N + n];
            const float bv  = base_var [k * N + n];
            w   = mix_p[k * N + n];
            inv = rsqrtf(qd * qd * bv);
            basec = (-qd * bm - q0) * inv;
            const float rinv = __frcp_rn(inv);
            // cc crosses -5.5 at tlo, +5.5 at thi (cc increasing in j)
            const float tlo = fmaf(-5.5f - basec, rinv, 128.0f);
            const float thi = fmaf( 5.5f - basec, rinv, 128.0f);
            // j < jlo: Phi exact 0 (incl. forced e_0); j >= jsat: Phi exact 1
            // (incl. forced e_256)
            jlo  = __float2int_rd(fminf(fmaxf(tlo, 1.0f), 256.0f));
            jsat = __float2int_ru(fminf(fmaxf(thi, 0.0f), 256.0f));
            if (jsat < jlo) jsat = jlo;
        }
        s_kc[warp][lane] = make_float4(basec, inv, w,
                                       __int_as_float(jlo | ((jsat - jlo) << 16)));
        atomicAdd(&s_AM[warp][1][jsat], w);    // marker: step mass at jsat
    }
    __syncwarp();

    // ---- 8 fully-unrolled scatter passes into this warp's accumulator ----
    {
        float* __restrict__ acc = &s_AM[warp][0][0];
        #pragma unroll
        for (int p = 0; p < NW; ++p) {
            const float4 c   = s_kc[warp][p];           // LDS.128 broadcast
            const int    pk  = __float_as_int(c.w);
            const int    jlo = pk & 0xffff;
            const int    nE  = pk >> 16;                // <= ~22 here
            if (lane < nE) {
                const float cc = fmaf((float)(jlo + lane - 128), c.y, c.x);
                acc[jlo + lane] += c.z * phi_fast(cc);  // conflict-free RMW
            }
            if (nE > 32) {                              // cold, never taken here
                for (int i = 32 + lane; i < nE; i += 32) {
                    const float cc = fmaf((float)(jlo + i - 128), c.y, c.x);
                    acc[jlo + i] += c.z * phi_fast(cc);
                }
            }
        }
    }
    __syncthreads();                                    // the only block barrier

    // ---- reduce + diff + coalesced store ----
    {
        float d = 0.0f;
        #pragma unroll
        for (int i = 0; i < NW; ++i)
            d += s_AM[i][0][tid + 1] - s_AM[i][0][tid]  // A[0]=A[256]=0 by constr.
               + s_AM[i][1][tid + 1];                   // markers
        out[(size_t)n * NBINS + tid] = d;
    }
}

extern "C" void kernel_launch(void* const* d_in, const int* in_sizes, int n_in,
                              void* d_out, int out_size)
{
    const float* Q     = (const float*)d_in[0];   // [N, N]
    const float* Q0    = (const float*)d_in[1];   // [N, 1]
    const float* bmean = (const float*)d_in[2];   // [K, N]
    const float* bvar  = (const float*)d_in[3];   // [K, N]
    const float* mp    = (const float*)d_in[4];   // [K, N, 1]
    float* out = (float*)d_out;                   // [N, 256]

    const int N = in_sizes[1];                    // 1024
    const int K = in_sizes[2] / N;                // 64

    spnbp_kernel<<<N, TPB>>>(Q, Q0, bmean, bvar, mp, out, N, K);
}